// round 14
// baseline (speedup 1.0000x reference)
#include <cuda_runtime.h>
#include <cuda_fp16.h>
#include <cstdint>

// Problem constants
#define NB    4
#define LSEQ  2048
#define HH    16
#define DD    32
#define DIMM  512
#define MROWS (NB*LSEQ)      // 8192
#define TCH   128            // chunk length
#define CCH   (LSEQ/TCH)     // 16 chunks

// ---------------- scratch (device globals; no allocations) ----------------
__device__ __half g_Q16[(size_t)MROWS*DIMM];
__device__ __half g_K16[(size_t)MROWS*DIMM];
__device__ __half g_V16[(size_t)MROWS*DIMM];
__device__ float  g_CS[(size_t)NB*HH*CCH*DD*DD];

// ---------------- PTX helpers ----------------------------------------------
__device__ __forceinline__ void ldmx4(uint32_t addr, uint32_t* r) {
    asm volatile("ldmatrix.sync.aligned.m8n8.x4.shared.b16 {%0,%1,%2,%3}, [%4];"
        : "=r"(r[0]), "=r"(r[1]), "=r"(r[2]), "=r"(r[3]) : "r"(addr));
}
__device__ __forceinline__ void ldmx4t(uint32_t addr, uint32_t* r) {
    asm volatile("ldmatrix.sync.aligned.m8n8.x4.trans.shared.b16 {%0,%1,%2,%3}, [%4];"
        : "=r"(r[0]), "=r"(r[1]), "=r"(r[2]), "=r"(r[3]) : "r"(addr));
}
__device__ __forceinline__ void mma16816(float* d, const uint32_t* a, const uint32_t* b) {
    asm volatile("mma.sync.aligned.m16n8k16.row.col.f32.f16.f16.f32 "
        "{%0,%1,%2,%3}, {%4,%5,%6,%7}, {%8,%9}, {%0,%1,%2,%3};"
        : "+f"(d[0]), "+f"(d[1]), "+f"(d[2]), "+f"(d[3])
        : "r"(a[0]), "r"(a[1]), "r"(a[2]), "r"(a[3]), "r"(b[0]), "r"(b[1]));
}
__device__ __forceinline__ void cp_async16(uint32_t dst, const void* src) {
    asm volatile("cp.async.cg.shared.global [%0], [%1], 16;" :: "r"(dst), "l"(src) : "memory");
}
#define CP_COMMIT()  asm volatile("cp.async.commit_group;" ::: "memory")
#define CP_WAIT(n)   asm volatile("cp.async.wait_group %0;" :: "n"(n) : "memory")
#define SW128(off)   ((off) ^ (((off) >> 3) & 0x70u))

__device__ __forceinline__ uint32_t smem_u32(const void* p) {
    uint32_t a;
    asm("{ .reg .u64 t; cvta.to.shared.u64 t, %1; cvt.u32.u64 %0, t; }" : "=r"(a) : "l"(p));
    return a;
}
__device__ __forceinline__ uint32_t h2(float x, float y) {
    __half2 t = __floats2half2_rn(x, y);
    return *(uint32_t*)&t;
}

// ---------------- Kernel 1: HMMA projection + fused cvt + softmax ----------
// CTA tile 128m x 128n, K staged 64, double buffer (2x32KB) -> 2 CTA/SM.
// Loads fp32 X/W, converts to fp16 in registers, STS into staged smem.
#define PROJ_STAGE  32768
#define PROJ_SMEM_BYTES (2 * PROJ_STAGE)
__global__ __launch_bounds__(256, 2) void proj_mma(
    const float* __restrict__ query, const float* __restrict__ key,
    const float* __restrict__ Wq, const float* __restrict__ Wk,
    const float* __restrict__ Wv)
{
    extern __shared__ char smem[];
    uint32_t smem_base = smem_u32(smem);
    const int tid = threadIdx.x, wid = tid >> 5, lane = tid & 31;
    const int n0 = blockIdx.x * 128, m0 = blockIdx.y * 128, gz = blockIdx.z;
    const float* Xf = (gz == 0) ? query : key;
    const float* Wf = (gz == 0) ? Wq : (gz == 1 ? Wk : Wv);
    __half* Y16 = (gz == 0) ? g_Q16 : (gz == 1 ? g_K16 : g_V16);

    const int m_base = (wid >> 1) * 32;              // 4 m-warps (32 rows each)
    const int n_base = (wid & 1) * 64;               // 2 n-warps (64 cols each)

    const int lrow = tid >> 3, lseg = tid & 7;       // loader geometry

    float acc[2][8][4] = {};                         // [mfrag16][nfrag8][reg]
    uint32_t st[32];                                 // staged fp16 regs

    auto load_regs = [&](int kc) {
        #pragma unroll
        for (int r = 0; r < 4; r++) {
            int row = lrow + r * 32;
            size_t ga = (size_t)(m0 + row) * DIMM + (size_t)kc * 64 + lseg * 8;
            float4 v0 = *(const float4*)(Xf + ga);
            float4 v1 = *(const float4*)(Xf + ga + 4);
            st[r*4+0] = h2(v0.x, v0.y); st[r*4+1] = h2(v0.z, v0.w);
            st[r*4+2] = h2(v1.x, v1.y); st[r*4+3] = h2(v1.z, v1.w);
        }
        #pragma unroll
        for (int r = 0; r < 4; r++) {
            int row = lrow + r * 32;
            size_t gb = (size_t)(n0 + row) * DIMM + (size_t)kc * 64 + lseg * 8;
            float4 v0 = *(const float4*)(Wf + gb);
            float4 v1 = *(const float4*)(Wf + gb + 4);
            st[16+r*4+0] = h2(v0.x, v0.y); st[16+r*4+1] = h2(v0.z, v0.w);
            st[16+r*4+2] = h2(v1.x, v1.y); st[16+r*4+3] = h2(v1.z, v1.w);
        }
    };
    // NOTE: byte OFFSETS from the generic smem pointer (not shared-window addrs)
    auto store_stage = [&](int kc) {
        const uint32_t off0 = (uint32_t)(kc & 1) * PROJ_STAGE;
        #pragma unroll
        for (int r = 0; r < 4; r++) {
            int row = lrow + r * 32;
            uint32_t sw = SW128((uint32_t)(row * 128 + lseg * 16));
            *(uint4*)(smem + off0 + sw) =
                make_uint4(st[r*4+0], st[r*4+1], st[r*4+2], st[r*4+3]);
            *(uint4*)(smem + off0 + 16384 + sw) =
                make_uint4(st[16+r*4+0], st[16+r*4+1], st[16+r*4+2], st[16+r*4+3]);
        }
    };

    load_regs(0);
    store_stage(0);
    __syncthreads();
    for (int kc = 0; kc < 8; kc++) {
        if (kc < 7) load_regs(kc + 1);   // LDG latency hidden under MMAs
        const uint32_t stg = smem_base + (uint32_t)(kc & 1) * PROJ_STAGE;

        #pragma unroll
        for (int t = 0; t < 4; t++) {
            const int kbyte = t * 32;
            uint32_t a[2][4];
            #pragma unroll
            for (int f = 0; f < 2; f++) {
                uint32_t boff = (uint32_t)((m_base + f * 16 + (lane & 15)) * 128
                               + kbyte + ((lane >> 4) * 16));
                ldmx4(stg + SW128(boff), a[f]);
            }
            #pragma unroll
            for (int p = 0; p < 4; p++) {
                int row = n_base + p * 16 + (lane & 7) + ((lane & 16) >> 1);
                uint32_t boff = (uint32_t)(row * 128 + kbyte + (lane & 8) * 2);
                uint32_t rh[4];
                ldmx4(stg + 16384 + SW128(boff), rh);
                #pragma unroll
                for (int s = 0; s < 2; s++) {
                    int nf = p * 2 + s;
                    mma16816(acc[0][nf], a[0], rh + s * 2);
                    mma16816(acc[1][nf], a[1], rh + s * 2);
                }
            }
        }
        __syncthreads();
        if (kc < 7) { store_stage(kc + 1); __syncthreads(); }
    }

    // fused softmax over 32-col head groups (g=0: nf0-3, g=1: nf4-7)
    if (gz < 2) {
        #pragma unroll
        for (int f = 0; f < 2; f++) {
            #pragma unroll
            for (int g = 0; g < 2; g++) {
                float mx0 = -1e30f, mx1 = -1e30f;
                #pragma unroll
                for (int nf = g*4; nf < g*4+4; nf++) {
                    mx0 = fmaxf(mx0, fmaxf(acc[f][nf][0], acc[f][nf][1]));
                    mx1 = fmaxf(mx1, fmaxf(acc[f][nf][2], acc[f][nf][3]));
                }
                mx0 = fmaxf(mx0, __shfl_xor_sync(~0u, mx0, 1));
                mx0 = fmaxf(mx0, __shfl_xor_sync(~0u, mx0, 2));
                mx1 = fmaxf(mx1, __shfl_xor_sync(~0u, mx1, 1));
                mx1 = fmaxf(mx1, __shfl_xor_sync(~0u, mx1, 2));
                float s0 = 0.f, s1 = 0.f;
                #pragma unroll
                for (int nf = g*4; nf < g*4+4; nf++) {
                    acc[f][nf][0] = __expf(acc[f][nf][0] - mx0);
                    acc[f][nf][1] = __expf(acc[f][nf][1] - mx0);
                    acc[f][nf][2] = __expf(acc[f][nf][2] - mx1);
                    acc[f][nf][3] = __expf(acc[f][nf][3] - mx1);
                    s0 += acc[f][nf][0] + acc[f][nf][1];
                    s1 += acc[f][nf][2] + acc[f][nf][3];
                }
                s0 += __shfl_xor_sync(~0u, s0, 1);
                s0 += __shfl_xor_sync(~0u, s0, 2);
                s1 += __shfl_xor_sync(~0u, s1, 1);
                s1 += __shfl_xor_sync(~0u, s1, 2);
                float r0 = 1.f / s0, r1 = 1.f / s1;
                #pragma unroll
                for (int nf = g*4; nf < g*4+4; nf++) {
                    acc[f][nf][0] *= r0; acc[f][nf][1] *= r0;
                    acc[f][nf][2] *= r1; acc[f][nf][3] *= r1;
                }
            }
        }
    }

    // store fp16
    const int r0 = lane >> 2, c0 = (lane & 3) * 2;
    #pragma unroll
    for (int f = 0; f < 2; f++) {
        int row = m0 + m_base + f * 16 + r0;
        #pragma unroll
        for (int nf = 0; nf < 8; nf++) {
            int col = n0 + n_base + nf * 8 + c0;
            *(uint32_t*)&Y16[(size_t)row * DIMM + col] = h2(acc[f][nf][0], acc[f][nf][1]);
            *(uint32_t*)&Y16[(size_t)(row + 8) * DIMM + col] = h2(acc[f][nf][2], acc[f][nf][3]);
        }
    }
}

// ---------------- Kernel 2: HMMA chunk sums CS = K^T V ---------------------
#define TS 80   // smem row stride bytes (64B data + 16 pad)
__global__ __launch_bounds__(64) void chunk_sum()
{
    __shared__ char sm[2 * 128 * TS];
    uint32_t sb = smem_u32(sm);
    const uint32_t K_s = sb, V_s = sb + 128*TS;
    const int c = blockIdx.x, h = blockIdx.y, n = blockIdx.z;
    const int tid = threadIdx.x, w = tid >> 5, lane = tid & 31;
    const size_t base = ((size_t)(n * LSEQ + c * TCH)) * DIMM + h * DD;

    #pragma unroll
    for (int r = 0; r < 8; r++) {
        int idx = tid + r * 64;       // 0..511
        int row = idx >> 2, seg = idx & 3;
        size_t g = base + (size_t)row * DIMM + seg * 8;
        uint32_t so = (uint32_t)(row * TS + seg * 16);
        cp_async16(K_s + so, g_K16 + g);
        cp_async16(V_s + so, g_V16 + g);
    }
    CP_COMMIT();
    CP_WAIT(0);
    __syncthreads();

    const int m0 = w * 16;
    float acc[4][4] = {};
    const uint32_t a_off = (uint32_t)(((lane & 7) + ((lane >> 4) << 3)) * TS
                         + (m0 + ((lane >> 3) & 1) * 8) * 2);
    const uint32_t b_off = (uint32_t)((lane & 15) * TS + ((lane >> 4) * 8) * 2);

    #pragma unroll
    for (int kk = 0; kk < 8; kk++) {
        const uint32_t krow = (uint32_t)(kk * 16) * TS;
        uint32_t a[4];
        ldmx4t(K_s + krow + a_off, a);
        #pragma unroll
        for (int q = 0; q < 2; q++) {
            uint32_t b[4];
            ldmx4t(V_s + krow + b_off + q * 32, b);
            mma16816(acc[q*2],   a, b);
            mma16816(acc[q*2+1], a, b + 2);
        }
    }
    size_t ob = ((size_t)((n * HH + h) * CCH + c)) * 1024;
    const int dr = m0 + (lane >> 2), ec = (lane & 3) * 2;
    #pragma unroll
    for (int nf = 0; nf < 4; nf++) {
        *(float2*)&g_CS[ob + (size_t)dr * 32 + nf * 8 + ec] = make_float2(acc[nf][0], acc[nf][1]);
        *(float2*)&g_CS[ob + (size_t)(dr + 8) * 32 + nf * 8 + ec] = make_float2(acc[nf][2], acc[nf][3]);
    }
}

// ---------------- Kernel 3: HMMA intra-chunk causal attention --------------
#define ATTN_SMEM_BYTES (3*128*TS + 32*TS)
__global__ __launch_bounds__(256, 4) void chunk_attn(float* __restrict__ out)
{
    extern __shared__ char sm[];
    uint32_t sb = smem_u32(sm);
    const uint32_t Q_s = sb, K_s = sb + 128*TS, V_s = sb + 2*128*TS;
    const uint32_t S_s = sb + 3*128*TS;

    const int c = blockIdx.x, h = blockIdx.y, n = blockIdx.z;
    const int tid = threadIdx.x, wid = tid >> 5, lane = tid & 31;
    const size_t base = ((size_t)(n * LSEQ + c * TCH)) * DIMM + h * DD;

    // async fills (overlap with prefix LDGs below)
    #pragma unroll
    for (int r = 0; r < 2; r++) {
        int idx = tid + r * 256;      // 0..511
        int row = idx >> 2, seg = idx & 3;
        size_t g = base + (size_t)row * DIMM + seg * 8;
        uint32_t so = (uint32_t)(row * TS + seg * 16);
        cp_async16(Q_s + so, g_Q16 + g);
        cp_async16(K_s + so, g_K16 + g);
        cp_async16(V_s + so, g_V16 + g);
    }
    CP_COMMIT();

    {   // exclusive prefix S0 = sum of CS over chunks < c, fp16 to smem
        size_t cb = ((size_t)((n * HH + h) * CCH)) * 1024 + (size_t)tid * 4;
        float4 v = make_float4(0.f, 0.f, 0.f, 0.f);
        for (int cc = 0; cc < c; cc++) {
            float4 t4 = *(const float4*)&g_CS[cb + (size_t)cc * 1024];
            v.x += t4.x; v.y += t4.y; v.z += t4.z; v.w += t4.w;
        }
        int d = tid >> 3, e0 = (tid & 7) * 4;
        uint32_t so = (uint32_t)(d * TS + e0 * 2);
        *(uint2*)(sm + 3*128*TS + so) = make_uint2(h2(v.x, v.y), h2(v.z, v.w));
    }
    CP_WAIT(0);
    __syncthreads();

    const int G = wid;                // row-group per warp
    const int m_base = G * 16;

    uint32_t qh[2][4];
    {
        uint32_t a_off = (uint32_t)((m_base + (lane & 15)) * TS + (lane >> 4) * 16);
        ldmx4(Q_s + a_off,      qh[0]);
        ldmx4(Q_s + a_off + 32, qh[1]);
    }

    float o[4][4] = {};
    const uint32_t b_base = (uint32_t)(((lane & 7) + ((lane & 16) >> 1)) * TS + (lane & 8) * 2);
    const uint32_t bt_off = (uint32_t)((lane & 15) * TS + ((lane >> 4) * 8) * 2);

    // causal: column-group g contributes only for g <= G
    for (int g = 0; g <= G; g++) {
        float A0[4] = {}, A1[4] = {};
        #pragma unroll
        for (int kk = 0; kk < 2; kk++) {
            uint32_t off = b_base + (uint32_t)(g * 16) * TS + kk * 32;
            uint32_t bh[4];
            ldmx4(K_s + off, bh);
            mma16816(A0, qh[kk], bh);
            mma16816(A1, qh[kk], bh + 2);
        }
        if (g == G) {   // diagonal group: causal mask
            const int i0 = m_base + (lane >> 2), i1 = i0 + 8;
            const int jb = (lane & 3) * 2;
            int j0 = g * 16 + jb;
            if (j0     > i0) A0[0] = 0.f;
            if (j0 + 1 > i0) A0[1] = 0.f;
            if (j0     > i1) A0[2] = 0.f;
            if (j0 + 1 > i1) A0[3] = 0.f;
            int j1 = j0 + 8;
            if (j1     > i0) A1[0] = 0.f;
            if (j1 + 1 > i0) A1[1] = 0.f;
            if (j1     > i1) A1[2] = 0.f;
            if (j1 + 1 > i1) A1[3] = 0.f;
        }
        uint32_t ah[4];
        ah[0] = h2(A0[0], A0[1]); ah[1] = h2(A0[2], A0[3]);
        ah[2] = h2(A1[0], A1[1]); ah[3] = h2(A1[2], A1[3]);
        const uint32_t krow = (uint32_t)(g * 16) * TS;
        #pragma unroll
        for (int q = 0; q < 2; q++) {
            uint32_t bh[4];
            ldmx4t(V_s + krow + bt_off + q * 32, bh);
            mma16816(o[q*2],   ah, bh);
            mma16816(o[q*2+1], ah, bh + 2);
        }
    }

    // o += Q @ S0
    #pragma unroll
    for (int kk = 0; kk < 2; kk++) {
        const uint32_t krow = (uint32_t)(kk * 16) * TS;
        #pragma unroll
        for (int q = 0; q < 2; q++) {
            uint32_t bh[4];
            ldmx4t(S_s + krow + bt_off + q * 32, bh);
            mma16816(o[q*2],   qh[kk], bh);
            mma16816(o[q*2+1], qh[kk], bh + 2);
        }
    }

    const int r0 = lane >> 2, ec = (lane & 3) * 2;
    #pragma unroll
    for (int nf = 0; nf < 4; nf++) {
        size_t p0 = base + (size_t)(m_base + r0) * DIMM + nf * 8 + ec;
        *(float2*)&out[p0]              = make_float2(o[nf][0], o[nf][1]);
        *(float2*)&out[p0 + 8 * DIMM]   = make_float2(o[nf][2], o[nf][3]);
    }
}

// ---------------- launch ---------------------------------------------------
extern "C" void kernel_launch(void* const* d_in, const int* in_sizes, int n_in,
                              void* d_out, int out_size)
{
    const float* query = (const float*)d_in[0];
    const float* key   = (const float*)d_in[1];
    const float* Wq    = (const float*)d_in[2];
    const float* Wk    = (const float*)d_in[3];
    const float* Wv    = (const float*)d_in[4];
    float* out = (float*)d_out;

    cudaFuncSetAttribute(proj_mma, cudaFuncAttributeMaxDynamicSharedMemorySize,
                         PROJ_SMEM_BYTES);
    cudaFuncSetAttribute(chunk_attn, cudaFuncAttributeMaxDynamicSharedMemorySize,
                         ATTN_SMEM_BYTES);

    // 1) projections + fused fp32->fp16 convert + softmax
    proj_mma<<<dim3(DIMM / 128, MROWS / 128, 3), 256, PROJ_SMEM_BYTES>>>(
        query, key, Wq, Wk, Wv);
    // 2) per-chunk K^T V sums
    chunk_sum<<<dim3(CCH, HH, NB), 64>>>();
    // 3) intra-chunk causal attention (computes own prefix) + output
    chunk_attn<<<dim3(CCH, HH, NB), 256, ATTN_SMEM_BYTES>>>(out);
}

// round 15
// speedup vs baseline: 1.2593x; 1.2593x over previous
#include <cuda_runtime.h>
#include <cuda_fp16.h>
#include <cstdint>

// Problem constants
#define NB    4
#define LSEQ  2048
#define HH    16
#define DD    32
#define DIMM  512
#define MROWS (NB*LSEQ)      // 8192
#define TCH   128            // chunk length
#define CCH   (LSEQ/TCH)     // 16 chunks

// ---------------- scratch (device globals; no allocations) ----------------
__device__ __half g_Q16[(size_t)MROWS*DIMM];
__device__ __half g_K16[(size_t)MROWS*DIMM];
__device__ __half g_V16[(size_t)MROWS*DIMM];
__device__ float  g_CS[(size_t)NB*HH*CCH*DD*DD];
__device__ __half g_X16[(size_t)2*MROWS*DIMM];  // query rows then key rows
__device__ __half g_W16[(size_t)3*DIMM*DIMM];   // Wq, Wk, Wv

// ---------------- PTX helpers ----------------------------------------------
__device__ __forceinline__ void ldmx4(uint32_t addr, uint32_t* r) {
    asm volatile("ldmatrix.sync.aligned.m8n8.x4.shared.b16 {%0,%1,%2,%3}, [%4];"
        : "=r"(r[0]), "=r"(r[1]), "=r"(r[2]), "=r"(r[3]) : "r"(addr));
}
__device__ __forceinline__ void ldmx4t(uint32_t addr, uint32_t* r) {
    asm volatile("ldmatrix.sync.aligned.m8n8.x4.trans.shared.b16 {%0,%1,%2,%3}, [%4];"
        : "=r"(r[0]), "=r"(r[1]), "=r"(r[2]), "=r"(r[3]) : "r"(addr));
}
__device__ __forceinline__ void mma16816(float* d, const uint32_t* a, const uint32_t* b) {
    asm volatile("mma.sync.aligned.m16n8k16.row.col.f32.f16.f16.f32 "
        "{%0,%1,%2,%3}, {%4,%5,%6,%7}, {%8,%9}, {%0,%1,%2,%3};"
        : "+f"(d[0]), "+f"(d[1]), "+f"(d[2]), "+f"(d[3])
        : "r"(a[0]), "r"(a[1]), "r"(a[2]), "r"(a[3]), "r"(b[0]), "r"(b[1]));
}
__device__ __forceinline__ void cp_async16(uint32_t dst, const void* src) {
    asm volatile("cp.async.cg.shared.global [%0], [%1], 16;" :: "r"(dst), "l"(src) : "memory");
}
#define CP_COMMIT()  asm volatile("cp.async.commit_group;" ::: "memory")
#define CP_WAIT(n)   asm volatile("cp.async.wait_group %0;" :: "n"(n) : "memory")
#define SW128(off)   ((off) ^ (((off) >> 3) & 0x70u))

__device__ __forceinline__ uint32_t smem_u32(const void* p) {
    uint32_t a;
    asm("{ .reg .u64 t; cvta.to.shared.u64 t, %1; cvt.u32.u64 %0, t; }" : "=r"(a) : "l"(p));
    return a;
}
__device__ __forceinline__ uint32_t h2(float x, float y) {
    __half2 t = __floats2half2_rn(x, y);
    return *(uint32_t*)&t;
}

// ---------------- Kernel 0: fp32 -> fp16 convert (inputs) ------------------
__global__ __launch_bounds__(256) void cvt_fp16(
    const float* __restrict__ query, const float* __restrict__ key,
    const float* __restrict__ Wq, const float* __restrict__ Wk,
    const float* __restrict__ Wv)
{
    const size_t XQ = (size_t)2 * MROWS * DIMM / 4;
    const size_t WQ = (size_t)DIMM * DIMM / 4;
    size_t qi = (size_t)blockIdx.x * 256 + threadIdx.x;
    const float* src; __half* dst; size_t si;
    if (qi < XQ) {
        size_t half_ = XQ / 2;
        src = (qi < half_) ? query : key;
        si = (qi < half_) ? qi : qi - half_;
        dst = g_X16 + qi * 4;
    } else {
        size_t wi = qi - XQ;
        if (wi >= 3 * WQ) return;
        int w = (int)(wi / WQ);
        src = (w == 0) ? Wq : (w == 1 ? Wk : Wv);
        si = wi - (size_t)w * WQ;
        dst = g_W16 + wi * 4;
    }
    float4 v = *(const float4*)(src + si * 4);
    *(uint2*)dst = make_uint2(h2(v.x, v.y), h2(v.z, v.w));
}

// ---------------- Kernel 1: HMMA projection + fused softmax ----------------
// CTA tile 128m x 128n, K staged 64, double buffer (2x32KB) -> 2 CTA/SM.
#define PROJ_STAGE  32768
#define PROJ_SMEM_BYTES (2 * PROJ_STAGE)
__global__ __launch_bounds__(256, 2) void proj_mma()
{
    extern __shared__ char smem[];
    uint32_t smem_base = smem_u32(smem);
    const int tid = threadIdx.x, wid = tid >> 5, lane = tid & 31;
    const int n0 = blockIdx.x * 128, m0 = blockIdx.y * 128, gz = blockIdx.z;
    const size_t a_row0 = (size_t)(gz == 0 ? 0 : MROWS) + m0;
    const __half* W16 = g_W16 + (size_t)gz * DIMM * DIMM;
    __half* Y16 = (gz == 0) ? g_Q16 : (gz == 1 ? g_K16 : g_V16);

    const int m_base = (wid >> 1) * 32;              // 4 m-warps (32 rows each)
    const int n_base = (wid & 1) * 64;               // 2 n-warps (64 cols each)

    float acc[2][8][4] = {};                         // [mfrag16][nfrag8][reg]

    auto load_stage = [&](int kc) {
        const uint32_t stg = smem_base + (uint32_t)(kc & 1) * PROJ_STAGE;
        #pragma unroll
        for (int r = 0; r < 4; r++) {
            int idx = tid + r * 256;                 // 0..1023
            int row = idx >> 3, seg = idx & 7;
            uint32_t sw = SW128((uint32_t)(row * 128 + seg * 16));
            size_t ga = (a_row0 + row) * DIMM + (size_t)kc * 64 + seg * 8;
            size_t gb = (size_t)(n0 + row) * DIMM + (size_t)kc * 64 + seg * 8;
            cp_async16(stg + sw,          g_X16 + ga);
            cp_async16(stg + 16384 + sw,  W16 + gb);
        }
        CP_COMMIT();
    };

    load_stage(0);
    for (int kc = 0; kc < 8; kc++) {
        if (kc < 7) { load_stage(kc + 1); CP_WAIT(1); }
        else        { CP_WAIT(0); }
        __syncthreads();
        const uint32_t stg = smem_base + (uint32_t)(kc & 1) * PROJ_STAGE;

        #pragma unroll
        for (int t = 0; t < 4; t++) {
            const int kbyte = t * 32;
            uint32_t a[2][4];
            #pragma unroll
            for (int f = 0; f < 2; f++) {
                uint32_t boff = (uint32_t)((m_base + f * 16 + (lane & 15)) * 128
                               + kbyte + ((lane >> 4) * 16));
                ldmx4(stg + SW128(boff), a[f]);
            }
            #pragma unroll
            for (int p = 0; p < 4; p++) {
                int row = n_base + p * 16 + (lane & 7) + ((lane & 16) >> 1);
                uint32_t boff = (uint32_t)(row * 128 + kbyte + (lane & 8) * 2);
                uint32_t rh[4];
                ldmx4(stg + 16384 + SW128(boff), rh);
                #pragma unroll
                for (int s = 0; s < 2; s++) {
                    int nf = p * 2 + s;
                    mma16816(acc[0][nf], a[0], rh + s * 2);
                    mma16816(acc[1][nf], a[1], rh + s * 2);
                }
            }
        }
        __syncthreads();
    }

    // fused softmax over 32-col head groups (g=0: nf0-3, g=1: nf4-7)
    if (gz < 2) {
        #pragma unroll
        for (int f = 0; f < 2; f++) {
            #pragma unroll
            for (int g = 0; g < 2; g++) {
                float mx0 = -1e30f, mx1 = -1e30f;
                #pragma unroll
                for (int nf = g*4; nf < g*4+4; nf++) {
                    mx0 = fmaxf(mx0, fmaxf(acc[f][nf][0], acc[f][nf][1]));
                    mx1 = fmaxf(mx1, fmaxf(acc[f][nf][2], acc[f][nf][3]));
                }
                mx0 = fmaxf(mx0, __shfl_xor_sync(~0u, mx0, 1));
                mx0 = fmaxf(mx0, __shfl_xor_sync(~0u, mx0, 2));
                mx1 = fmaxf(mx1, __shfl_xor_sync(~0u, mx1, 1));
                mx1 = fmaxf(mx1, __shfl_xor_sync(~0u, mx1, 2));
                float s0 = 0.f, s1 = 0.f;
                #pragma unroll
                for (int nf = g*4; nf < g*4+4; nf++) {
                    acc[f][nf][0] = __expf(acc[f][nf][0] - mx0);
                    acc[f][nf][1] = __expf(acc[f][nf][1] - mx0);
                    acc[f][nf][2] = __expf(acc[f][nf][2] - mx1);
                    acc[f][nf][3] = __expf(acc[f][nf][3] - mx1);
                    s0 += acc[f][nf][0] + acc[f][nf][1];
                    s1 += acc[f][nf][2] + acc[f][nf][3];
                }
                s0 += __shfl_xor_sync(~0u, s0, 1);
                s0 += __shfl_xor_sync(~0u, s0, 2);
                s1 += __shfl_xor_sync(~0u, s1, 1);
                s1 += __shfl_xor_sync(~0u, s1, 2);
                float r0 = 1.f / s0, r1 = 1.f / s1;
                #pragma unroll
                for (int nf = g*4; nf < g*4+4; nf++) {
                    acc[f][nf][0] *= r0; acc[f][nf][1] *= r0;
                    acc[f][nf][2] *= r1; acc[f][nf][3] *= r1;
                }
            }
        }
    }

    // store fp16
    const int r0 = lane >> 2, c0 = (lane & 3) * 2;
    #pragma unroll
    for (int f = 0; f < 2; f++) {
        int row = m0 + m_base + f * 16 + r0;
        #pragma unroll
        for (int nf = 0; nf < 8; nf++) {
            int col = n0 + n_base + nf * 8 + c0;
            *(uint32_t*)&Y16[(size_t)row * DIMM + col] = h2(acc[f][nf][0], acc[f][nf][1]);
            *(uint32_t*)&Y16[(size_t)(row + 8) * DIMM + col] = h2(acc[f][nf][2], acc[f][nf][3]);
        }
    }
}

// ---------------- Kernel 2: HMMA chunk sums CS = K^T V ---------------------
#define TS 80   // smem row stride bytes (64B data + 16 pad)
__global__ __launch_bounds__(64) void chunk_sum()
{
    __shared__ char sm[2 * 128 * TS];
    uint32_t sb = smem_u32(sm);
    const uint32_t K_s = sb, V_s = sb + 128*TS;
    const int c = blockIdx.x, h = blockIdx.y, n = blockIdx.z;
    const int tid = threadIdx.x, w = tid >> 5, lane = tid & 31;
    const size_t base = ((size_t)(n * LSEQ + c * TCH)) * DIMM + h * DD;

    #pragma unroll
    for (int r = 0; r < 8; r++) {
        int idx = tid + r * 64;       // 0..511
        int row = idx >> 2, seg = idx & 3;
        size_t g = base + (size_t)row * DIMM + seg * 8;
        uint32_t so = (uint32_t)(row * TS + seg * 16);
        cp_async16(K_s + so, g_K16 + g);
        cp_async16(V_s + so, g_V16 + g);
    }
    CP_COMMIT();
    CP_WAIT(0);
    __syncthreads();

    const int m0 = w * 16;
    float acc[4][4] = {};
    const uint32_t a_off = (uint32_t)(((lane & 7) + ((lane >> 4) << 3)) * TS
                         + (m0 + ((lane >> 3) & 1) * 8) * 2);
    const uint32_t b_off = (uint32_t)((lane & 15) * TS + ((lane >> 4) * 8) * 2);

    #pragma unroll
    for (int kk = 0; kk < 8; kk++) {
        const uint32_t krow = (uint32_t)(kk * 16) * TS;
        uint32_t a[4];
        ldmx4t(K_s + krow + a_off, a);
        #pragma unroll
        for (int q = 0; q < 2; q++) {
            uint32_t b[4];
            ldmx4t(V_s + krow + b_off + q * 32, b);
            mma16816(acc[q*2],   a, b);
            mma16816(acc[q*2+1], a, b + 2);
        }
    }
    size_t ob = ((size_t)((n * HH + h) * CCH + c)) * 1024;
    const int dr = m0 + (lane >> 2), ec = (lane & 3) * 2;
    #pragma unroll
    for (int nf = 0; nf < 4; nf++) {
        *(float2*)&g_CS[ob + (size_t)dr * 32 + nf * 8 + ec] = make_float2(acc[nf][0], acc[nf][1]);
        *(float2*)&g_CS[ob + (size_t)(dr + 8) * 32 + nf * 8 + ec] = make_float2(acc[nf][2], acc[nf][3]);
    }
}

// ---------------- Kernel 3: HMMA intra-chunk causal attention --------------
#define ATTN_SMEM_BYTES (3*128*TS + 32*TS)
__global__ __launch_bounds__(256, 4) void chunk_attn(float* __restrict__ out)
{
    extern __shared__ char sm[];
    uint32_t sb = smem_u32(sm);
    const uint32_t Q_s = sb, K_s = sb + 128*TS, V_s = sb + 2*128*TS;
    const uint32_t S_s = sb + 3*128*TS;

    const int c = blockIdx.x, h = blockIdx.y, n = blockIdx.z;
    const int tid = threadIdx.x, wid = tid >> 5, lane = tid & 31;
    const size_t base = ((size_t)(n * LSEQ + c * TCH)) * DIMM + h * DD;

    // async fills (overlap with prefix LDGs below)
    #pragma unroll
    for (int r = 0; r < 2; r++) {
        int idx = tid + r * 256;      // 0..511
        int row = idx >> 2, seg = idx & 3;
        size_t g = base + (size_t)row * DIMM + seg * 8;
        uint32_t so = (uint32_t)(row * TS + seg * 16);
        cp_async16(Q_s + so, g_Q16 + g);
        cp_async16(K_s + so, g_K16 + g);
        cp_async16(V_s + so, g_V16 + g);
    }
    CP_COMMIT();

    {   // exclusive prefix S0 = sum of CS over chunks < c, fp16 to smem
        size_t cb = ((size_t)((n * HH + h) * CCH)) * 1024 + (size_t)tid * 4;
        float4 v = make_float4(0.f, 0.f, 0.f, 0.f);
        for (int cc = 0; cc < c; cc++) {
            float4 t4 = *(const float4*)&g_CS[cb + (size_t)cc * 1024];
            v.x += t4.x; v.y += t4.y; v.z += t4.z; v.w += t4.w;
        }
        int d = tid >> 3, e0 = (tid & 7) * 4;
        uint32_t so = (uint32_t)(d * TS + e0 * 2);
        *(uint2*)(sm + 3*128*TS + so) = make_uint2(h2(v.x, v.y), h2(v.z, v.w));
    }
    CP_WAIT(0);
    __syncthreads();

    const int G = wid;                // row-group per warp
    const int m_base = G * 16;

    uint32_t qh[2][4];
    {
        uint32_t a_off = (uint32_t)((m_base + (lane & 15)) * TS + (lane >> 4) * 16);
        ldmx4(Q_s + a_off,      qh[0]);
        ldmx4(Q_s + a_off + 32, qh[1]);
    }

    float o[4][4] = {};
    const uint32_t b_base = (uint32_t)(((lane & 7) + ((lane & 16) >> 1)) * TS + (lane & 8) * 2);
    const uint32_t bt_off = (uint32_t)((lane & 15) * TS + ((lane >> 4) * 8) * 2);

    // causal: column-group g contributes only for g <= G
    for (int g = 0; g <= G; g++) {
        float A0[4] = {}, A1[4] = {};
        #pragma unroll
        for (int kk = 0; kk < 2; kk++) {
            uint32_t off = b_base + (uint32_t)(g * 16) * TS + kk * 32;
            uint32_t bh[4];
            ldmx4(K_s + off, bh);
            mma16816(A0, qh[kk], bh);
            mma16816(A1, qh[kk], bh + 2);
        }
        if (g == G) {   // diagonal group: causal mask
            const int i0 = m_base + (lane >> 2), i1 = i0 + 8;
            const int jb = (lane & 3) * 2;
            int j0 = g * 16 + jb;
            if (j0     > i0) A0[0] = 0.f;
            if (j0 + 1 > i0) A0[1] = 0.f;
            if (j0     > i1) A0[2] = 0.f;
            if (j0 + 1 > i1) A0[3] = 0.f;
            int j1 = j0 + 8;
            if (j1     > i0) A1[0] = 0.f;
            if (j1 + 1 > i0) A1[1] = 0.f;
            if (j1     > i1) A1[2] = 0.f;
            if (j1 + 1 > i1) A1[3] = 0.f;
        }
        uint32_t ah[4];
        ah[0] = h2(A0[0], A0[1]); ah[1] = h2(A0[2], A0[3]);
        ah[2] = h2(A1[0], A1[1]); ah[3] = h2(A1[2], A1[3]);
        const uint32_t krow = (uint32_t)(g * 16) * TS;
        #pragma unroll
        for (int q = 0; q < 2; q++) {
            uint32_t bh[4];
            ldmx4t(V_s + krow + bt_off + q * 32, bh);
            mma16816(o[q*2],   ah, bh);
            mma16816(o[q*2+1], ah, bh + 2);
        }
    }

    // o += Q @ S0
    #pragma unroll
    for (int kk = 0; kk < 2; kk++) {
        const uint32_t krow = (uint32_t)(kk * 16) * TS;
        #pragma unroll
        for (int q = 0; q < 2; q++) {
            uint32_t bh[4];
            ldmx4t(S_s + krow + bt_off + q * 32, bh);
            mma16816(o[q*2],   qh[kk], bh);
            mma16816(o[q*2+1], qh[kk], bh + 2);
        }
    }

    const int r0 = lane >> 2, ec = (lane & 3) * 2;
    #pragma unroll
    for (int nf = 0; nf < 4; nf++) {
        size_t p0 = base + (size_t)(m_base + r0) * DIMM + nf * 8 + ec;
        *(float2*)&out[p0]              = make_float2(o[nf][0], o[nf][1]);
        *(float2*)&out[p0 + 8 * DIMM]   = make_float2(o[nf][2], o[nf][3]);
    }
}

// ---------------- launch ---------------------------------------------------
extern "C" void kernel_launch(void* const* d_in, const int* in_sizes, int n_in,
                              void* d_out, int out_size)
{
    const float* query = (const float*)d_in[0];
    const float* key   = (const float*)d_in[1];
    const float* Wq    = (const float*)d_in[2];
    const float* Wk    = (const float*)d_in[3];
    const float* Wv    = (const float*)d_in[4];
    float* out = (float*)d_out;

    cudaFuncSetAttribute(proj_mma, cudaFuncAttributeMaxDynamicSharedMemorySize,
                         PROJ_SMEM_BYTES);
    cudaFuncSetAttribute(chunk_attn, cudaFuncAttributeMaxDynamicSharedMemorySize,
                         ATTN_SMEM_BYTES);

    // 0) convert fp32 -> fp16 (X and W)
    {
        const size_t XQ = (size_t)2 * MROWS * DIMM / 4;
        const size_t WQ = (size_t)DIMM * DIMM / 4;
        int blocks = (int)((XQ + 3 * WQ + 255) / 256);
        cvt_fp16<<<blocks, 256>>>(query, key, Wq, Wk, Wv);
    }
    // 1) projections + fused softmax (fp16 HMMA, cp.async double buffer)
    proj_mma<<<dim3(DIMM / 128, MROWS / 128, 3), 256, PROJ_SMEM_BYTES>>>();
    // 2) per-chunk K^T V sums (cp.async fill)
    chunk_sum<<<dim3(CCH, HH, NB), 64>>>();
    // 3) intra-chunk causal attention (cp.async fill, own prefix) + output
    chunk_attn<<<dim3(CCH, HH, NB), 256, ATTN_SMEM_BYTES>>>(out);
}

// round 16
// speedup vs baseline: 1.2719x; 1.0100x over previous
#include <cuda_runtime.h>
#include <cuda_fp16.h>
#include <cstdint>

// Problem constants
#define NB    4
#define LSEQ  2048
#define HH    16
#define DD    32
#define DIMM  512
#define MROWS (NB*LSEQ)      // 8192
#define TCH   128            // chunk length
#define CCH   (LSEQ/TCH)     // 16 chunks

// ---------------- scratch (device globals; no allocations) ----------------
__device__ __half g_Q16[(size_t)MROWS*DIMM];
__device__ __half g_K16[(size_t)MROWS*DIMM];
__device__ __half g_V16[(size_t)MROWS*DIMM];
__device__ float  g_CS[(size_t)NB*HH*CCH*DD*DD];
__device__ __half g_W16[(size_t)3*DIMM*DIMM];   // Wq, Wk, Wv (fp16)

// ---------------- PTX helpers ----------------------------------------------
__device__ __forceinline__ void ldmx4(uint32_t addr, uint32_t* r) {
    asm volatile("ldmatrix.sync.aligned.m8n8.x4.shared.b16 {%0,%1,%2,%3}, [%4];"
        : "=r"(r[0]), "=r"(r[1]), "=r"(r[2]), "=r"(r[3]) : "r"(addr));
}
__device__ __forceinline__ void ldmx4t(uint32_t addr, uint32_t* r) {
    asm volatile("ldmatrix.sync.aligned.m8n8.x4.trans.shared.b16 {%0,%1,%2,%3}, [%4];"
        : "=r"(r[0]), "=r"(r[1]), "=r"(r[2]), "=r"(r[3]) : "r"(addr));
}
__device__ __forceinline__ void mma16816(float* d, const uint32_t* a, const uint32_t* b) {
    asm volatile("mma.sync.aligned.m16n8k16.row.col.f32.f16.f16.f32 "
        "{%0,%1,%2,%3}, {%4,%5,%6,%7}, {%8,%9}, {%0,%1,%2,%3};"
        : "+f"(d[0]), "+f"(d[1]), "+f"(d[2]), "+f"(d[3])
        : "r"(a[0]), "r"(a[1]), "r"(a[2]), "r"(a[3]), "r"(b[0]), "r"(b[1]));
}
__device__ __forceinline__ void cp_async16(uint32_t dst, const void* src) {
    asm volatile("cp.async.cg.shared.global [%0], [%1], 16;" :: "r"(dst), "l"(src) : "memory");
}
#define CP_COMMIT()  asm volatile("cp.async.commit_group;" ::: "memory")
#define CP_WAIT(n)   asm volatile("cp.async.wait_group %0;" :: "n"(n) : "memory")
#define SW128(off)   ((off) ^ (((off) >> 3) & 0x70u))

__device__ __forceinline__ uint32_t smem_u32(const void* p) {
    uint32_t a;
    asm("{ .reg .u64 t; cvta.to.shared.u64 t, %1; cvt.u32.u64 %0, t; }" : "=r"(a) : "l"(p));
    return a;
}
__device__ __forceinline__ uint32_t h2(float x, float y) {
    __half2 t = __floats2half2_rn(x, y);
    return *(uint32_t*)&t;
}
// load fp32 pair from shared, convert to packed fp16x2
__device__ __forceinline__ uint32_t lds2h(uint32_t addr) {
    float x, y;
    asm volatile("ld.shared.v2.f32 {%0,%1}, [%2];" : "=f"(x), "=f"(y) : "r"(addr));
    return h2(x, y);
}

// ---------------- Kernel 0: fp32 -> fp16 convert (W only) ------------------
__global__ __launch_bounds__(256) void cvt_w(
    const float* __restrict__ Wq, const float* __restrict__ Wk,
    const float* __restrict__ Wv)
{
    const size_t WQ = (size_t)DIMM * DIMM / 4;     // quads per W
    size_t wi = (size_t)blockIdx.x * 256 + threadIdx.x;
    if (wi >= 3 * WQ) return;
    int w = (int)(wi / WQ);
    const float* src = (w == 0) ? Wq : (w == 1 ? Wk : Wv);
    size_t si = wi - (size_t)w * WQ;
    float4 v = *(const float4*)(src + si * 4);
    *(uint2*)(g_W16 + wi * 4) = make_uint2(h2(v.x, v.y), h2(v.z, v.w));
}

// ---------------- Kernel 1: HMMA projection + fused cvt(A) + softmax -------
// CTA tile 128m x 128n, K staged 64, double buffer.
// Stage: A fp32 (32KB, 8B-unit XOR swizzle) | B fp16 (16KB, SW128) = 48KB.
#define PROJ_STAGE  49152
#define PROJ_A_BYTES 32768
#define PROJ_SMEM_BYTES (2 * PROJ_STAGE)
__global__ __launch_bounds__(256, 2) void proj_mma(
    const float* __restrict__ query, const float* __restrict__ key)
{
    extern __shared__ char smem[];
    uint32_t smem_base = smem_u32(smem);
    const int tid = threadIdx.x, wid = tid >> 5, lane = tid & 31;
    const int n0 = blockIdx.x * 128, m0 = blockIdx.y * 128, gz = blockIdx.z;
    const float* Xf = (gz == 0) ? query : key;
    const __half* W16 = g_W16 + (size_t)gz * DIMM * DIMM;
    __half* Y16 = (gz == 0) ? g_Q16 : (gz == 1 ? g_K16 : g_V16);

    const int m_base = (wid >> 1) * 32;              // 4 m-warps (32 rows each)
    const int n_base = (wid & 1) * 64;               // 2 n-warps (64 cols each)

    float acc[2][8][4] = {};                         // [mfrag16][nfrag8][reg]

    auto load_stage = [&](int kc) {
        const uint32_t stg = smem_base + (uint32_t)(kc & 1) * PROJ_STAGE;
        // A: 128 rows x 64 fp32 (256B/row), swizzle: unit x = u ^ ((row&7)<<2)
        #pragma unroll
        for (int r = 0; r < 8; r++) {
            int idx = tid + r * 256;                 // 0..2047
            int row = idx >> 4, seg16 = idx & 15;    // 16 x 16B per row
            int u = seg16 * 2;
            uint32_t x = (uint32_t)(u ^ ((row & 7) << 2));
            size_t ga = (size_t)(m0 + row) * DIMM + (size_t)kc * 64 + seg16 * 4;
            cp_async16(stg + (uint32_t)row * 256u + x * 8u, Xf + ga);
        }
        // B: 128 rows x 64 fp16 (128B/row), SW128
        #pragma unroll
        for (int r = 0; r < 4; r++) {
            int idx = tid + r * 256;                 // 0..1023
            int row = idx >> 3, seg = idx & 7;
            uint32_t sw = SW128((uint32_t)(row * 128 + seg * 16));
            size_t gb = (size_t)(n0 + row) * DIMM + (size_t)kc * 64 + seg * 8;
            cp_async16(stg + PROJ_A_BYTES + sw, W16 + gb);
        }
        CP_COMMIT();
    };

    load_stage(0);
    for (int kc = 0; kc < 8; kc++) {
        if (kc < 7) { load_stage(kc + 1); CP_WAIT(1); }
        else        { CP_WAIT(0); }
        __syncthreads();
        const uint32_t stg = smem_base + (uint32_t)(kc & 1) * PROJ_STAGE;
        const uint32_t bstg = stg + PROJ_A_BYTES;

        const uint32_t xk = (uint32_t)((lane >> 2) << 2);  // row&7 == lane>>2
        #pragma unroll
        for (int t = 0; t < 4; t++) {
            const int kbyte = t * 32;
            // A fragments from fp32 smem: 4 x LDS.64 + cvt per frag
            uint32_t a[2][4];
            #pragma unroll
            for (int f = 0; f < 2; f++) {
                uint32_t rlo = (uint32_t)(m_base + f * 16 + (lane >> 2));
                uint32_t rhi = rlo + 8;
                uint32_t u0 = (uint32_t)(t * 8 + (lane & 3));
                uint32_t x0 = (u0 ^ xk) * 8u, x1 = ((u0 + 4) ^ xk) * 8u;
                a[f][0] = lds2h(stg + rlo * 256u + x0);
                a[f][1] = lds2h(stg + rhi * 256u + x0);
                a[f][2] = lds2h(stg + rlo * 256u + x1);
                a[f][3] = lds2h(stg + rhi * 256u + x1);
            }
            #pragma unroll
            for (int p = 0; p < 4; p++) {
                int row = n_base + p * 16 + (lane & 7) + ((lane & 16) >> 1);
                uint32_t boff = (uint32_t)(row * 128 + kbyte + (lane & 8) * 2);
                uint32_t rh[4];
                ldmx4(bstg + SW128(boff), rh);
                #pragma unroll
                for (int s = 0; s < 2; s++) {
                    int nf = p * 2 + s;
                    mma16816(acc[0][nf], a[0], rh + s * 2);
                    mma16816(acc[1][nf], a[1], rh + s * 2);
                }
            }
        }
        __syncthreads();
    }

    // fused softmax over 32-col head groups (g=0: nf0-3, g=1: nf4-7)
    if (gz < 2) {
        #pragma unroll
        for (int f = 0; f < 2; f++) {
            #pragma unroll
            for (int g = 0; g < 2; g++) {
                float mx0 = -1e30f, mx1 = -1e30f;
                #pragma unroll
                for (int nf = g*4; nf < g*4+4; nf++) {
                    mx0 = fmaxf(mx0, fmaxf(acc[f][nf][0], acc[f][nf][1]));
                    mx1 = fmaxf(mx1, fmaxf(acc[f][nf][2], acc[f][nf][3]));
                }
                mx0 = fmaxf(mx0, __shfl_xor_sync(~0u, mx0, 1));
                mx0 = fmaxf(mx0, __shfl_xor_sync(~0u, mx0, 2));
                mx1 = fmaxf(mx1, __shfl_xor_sync(~0u, mx1, 1));
                mx1 = fmaxf(mx1, __shfl_xor_sync(~0u, mx1, 2));
                float s0 = 0.f, s1 = 0.f;
                #pragma unroll
                for (int nf = g*4; nf < g*4+4; nf++) {
                    acc[f][nf][0] = __expf(acc[f][nf][0] - mx0);
                    acc[f][nf][1] = __expf(acc[f][nf][1] - mx0);
                    acc[f][nf][2] = __expf(acc[f][nf][2] - mx1);
                    acc[f][nf][3] = __expf(acc[f][nf][3] - mx1);
                    s0 += acc[f][nf][0] + acc[f][nf][1];
                    s1 += acc[f][nf][2] + acc[f][nf][3];
                }
                s0 += __shfl_xor_sync(~0u, s0, 1);
                s0 += __shfl_xor_sync(~0u, s0, 2);
                s1 += __shfl_xor_sync(~0u, s1, 1);
                s1 += __shfl_xor_sync(~0u, s1, 2);
                float r0 = 1.f / s0, r1 = 1.f / s1;
                #pragma unroll
                for (int nf = g*4; nf < g*4+4; nf++) {
                    acc[f][nf][0] *= r0; acc[f][nf][1] *= r0;
                    acc[f][nf][2] *= r1; acc[f][nf][3] *= r1;
                }
            }
        }
    }

    // store fp16
    const int r0 = lane >> 2, c0 = (lane & 3) * 2;
    #pragma unroll
    for (int f = 0; f < 2; f++) {
        int row = m0 + m_base + f * 16 + r0;
        #pragma unroll
        for (int nf = 0; nf < 8; nf++) {
            int col = n0 + n_base + nf * 8 + c0;
            *(uint32_t*)&Y16[(size_t)row * DIMM + col] = h2(acc[f][nf][0], acc[f][nf][1]);
            *(uint32_t*)&Y16[(size_t)(row + 8) * DIMM + col] = h2(acc[f][nf][2], acc[f][nf][3]);
        }
    }
}

// ---------------- Kernel 2: HMMA chunk sums CS = K^T V ---------------------
#define TS 80   // smem row stride bytes (64B data + 16 pad)
__global__ __launch_bounds__(64) void chunk_sum()
{
    __shared__ char sm[2 * 128 * TS];
    uint32_t sb = smem_u32(sm);
    const uint32_t K_s = sb, V_s = sb + 128*TS;
    const int c = blockIdx.x, h = blockIdx.y, n = blockIdx.z;
    const int tid = threadIdx.x, w = tid >> 5, lane = tid & 31;
    const size_t base = ((size_t)(n * LSEQ + c * TCH)) * DIMM + h * DD;

    #pragma unroll
    for (int r = 0; r < 8; r++) {
        int idx = tid + r * 64;       // 0..511
        int row = idx >> 2, seg = idx & 3;
        size_t g = base + (size_t)row * DIMM + seg * 8;
        uint32_t so = (uint32_t)(row * TS + seg * 16);
        cp_async16(K_s + so, g_K16 + g);
        cp_async16(V_s + so, g_V16 + g);
    }
    CP_COMMIT();
    CP_WAIT(0);
    __syncthreads();

    const int m0 = w * 16;
    float acc[4][4] = {};
    const uint32_t a_off = (uint32_t)(((lane & 7) + ((lane >> 4) << 3)) * TS
                         + (m0 + ((lane >> 3) & 1) * 8) * 2);
    const uint32_t b_off = (uint32_t)((lane & 15) * TS + ((lane >> 4) * 8) * 2);

    #pragma unroll
    for (int kk = 0; kk < 8; kk++) {
        const uint32_t krow = (uint32_t)(kk * 16) * TS;
        uint32_t a[4];
        ldmx4t(K_s + krow + a_off, a);
        #pragma unroll
        for (int q = 0; q < 2; q++) {
            uint32_t b[4];
            ldmx4t(V_s + krow + b_off + q * 32, b);
            mma16816(acc[q*2],   a, b);
            mma16816(acc[q*2+1], a, b + 2);
        }
    }
    size_t ob = ((size_t)((n * HH + h) * CCH + c)) * 1024;
    const int dr = m0 + (lane >> 2), ec = (lane & 3) * 2;
    #pragma unroll
    for (int nf = 0; nf < 4; nf++) {
        *(float2*)&g_CS[ob + (size_t)dr * 32 + nf * 8 + ec] = make_float2(acc[nf][0], acc[nf][1]);
        *(float2*)&g_CS[ob + (size_t)(dr + 8) * 32 + nf * 8 + ec] = make_float2(acc[nf][2], acc[nf][3]);
    }
}

// ---------------- Kernel 3: HMMA intra-chunk causal attention --------------
#define ATTN_SMEM_BYTES (3*128*TS + 32*TS)
__global__ __launch_bounds__(256, 4) void chunk_attn(float* __restrict__ out)
{
    extern __shared__ char sm[];
    uint32_t sb = smem_u32(sm);
    const uint32_t Q_s = sb, K_s = sb + 128*TS, V_s = sb + 2*128*TS;
    const uint32_t S_s = sb + 3*128*TS;

    const int c = blockIdx.x, h = blockIdx.y, n = blockIdx.z;
    const int tid = threadIdx.x, wid = tid >> 5, lane = tid & 31;
    const size_t base = ((size_t)(n * LSEQ + c * TCH)) * DIMM + h * DD;

    // async fills (overlap with prefix LDGs below)
    #pragma unroll
    for (int r = 0; r < 2; r++) {
        int idx = tid + r * 256;      // 0..511
        int row = idx >> 2, seg = idx & 3;
        size_t g = base + (size_t)row * DIMM + seg * 8;
        uint32_t so = (uint32_t)(row * TS + seg * 16);
        cp_async16(Q_s + so, g_Q16 + g);
        cp_async16(K_s + so, g_K16 + g);
        cp_async16(V_s + so, g_V16 + g);
    }
    CP_COMMIT();

    {   // exclusive prefix S0 = sum of CS over chunks < c (MLP-4 unrolled)
        size_t cb = ((size_t)((n * HH + h) * CCH)) * 1024 + (size_t)tid * 4;
        float4 v = make_float4(0.f, 0.f, 0.f, 0.f);
        int cc = 0;
        for (; cc + 4 <= c; cc += 4) {
            float4 t0 = *(const float4*)&g_CS[cb + (size_t)(cc    ) * 1024];
            float4 t1 = *(const float4*)&g_CS[cb + (size_t)(cc + 1) * 1024];
            float4 t2 = *(const float4*)&g_CS[cb + (size_t)(cc + 2) * 1024];
            float4 t3 = *(const float4*)&g_CS[cb + (size_t)(cc + 3) * 1024];
            v.x += (t0.x + t1.x) + (t2.x + t3.x);
            v.y += (t0.y + t1.y) + (t2.y + t3.y);
            v.z += (t0.z + t1.z) + (t2.z + t3.z);
            v.w += (t0.w + t1.w) + (t2.w + t3.w);
        }
        for (; cc < c; cc++) {
            float4 t4 = *(const float4*)&g_CS[cb + (size_t)cc * 1024];
            v.x += t4.x; v.y += t4.y; v.z += t4.z; v.w += t4.w;
        }
        int d = tid >> 3, e0 = (tid & 7) * 4;
        uint32_t so = (uint32_t)(d * TS + e0 * 2);
        *(uint2*)(sm + 3*128*TS + so) = make_uint2(h2(v.x, v.y), h2(v.z, v.w));
    }
    CP_WAIT(0);
    __syncthreads();

    const int G = wid;                // row-group per warp
    const int m_base = G * 16;

    uint32_t qh[2][4];
    {
        uint32_t a_off = (uint32_t)((m_base + (lane & 15)) * TS + (lane >> 4) * 16);
        ldmx4(Q_s + a_off,      qh[0]);
        ldmx4(Q_s + a_off + 32, qh[1]);
    }

    float o[4][4] = {};
    const uint32_t b_base = (uint32_t)(((lane & 7) + ((lane & 16) >> 1)) * TS + (lane & 8) * 2);
    const uint32_t bt_off = (uint32_t)((lane & 15) * TS + ((lane >> 4) * 8) * 2);

    // causal: column-group g contributes only for g <= G
    for (int g = 0; g <= G; g++) {
        float A0[4] = {}, A1[4] = {};
        #pragma unroll
        for (int kk = 0; kk < 2; kk++) {
            uint32_t off = b_base + (uint32_t)(g * 16) * TS + kk * 32;
            uint32_t bh[4];
            ldmx4(K_s + off, bh);
            mma16816(A0, qh[kk], bh);
            mma16816(A1, qh[kk], bh + 2);
        }
        if (g == G) {   // diagonal group: causal mask
            const int i0 = m_base + (lane >> 2), i1 = i0 + 8;
            const int jb = (lane & 3) * 2;
            int j0 = g * 16 + jb;
            if (j0     > i0) A0[0] = 0.f;
            if (j0 + 1 > i0) A0[1] = 0.f;
            if (j0     > i1) A0[2] = 0.f;
            if (j0 + 1 > i1) A0[3] = 0.f;
            int j1 = j0 + 8;
            if (j1     > i0) A1[0] = 0.f;
            if (j1 + 1 > i0) A1[1] = 0.f;
            if (j1     > i1) A1[2] = 0.f;
            if (j1 + 1 > i1) A1[3] = 0.f;
        }
        uint32_t ah[4];
        ah[0] = h2(A0[0], A0[1]); ah[1] = h2(A0[2], A0[3]);
        ah[2] = h2(A1[0], A1[1]); ah[3] = h2(A1[2], A1[3]);
        const uint32_t krow = (uint32_t)(g * 16) * TS;
        #pragma unroll
        for (int q = 0; q < 2; q++) {
            uint32_t bh[4];
            ldmx4t(V_s + krow + bt_off + q * 32, bh);
            mma16816(o[q*2],   ah, bh);
            mma16816(o[q*2+1], ah, bh + 2);
        }
    }

    // o += Q @ S0
    #pragma unroll
    for (int kk = 0; kk < 2; kk++) {
        const uint32_t krow = (uint32_t)(kk * 16) * TS;
        #pragma unroll
        for (int q = 0; q < 2; q++) {
            uint32_t bh[4];
            ldmx4t(S_s + krow + bt_off + q * 32, bh);
            mma16816(o[q*2],   qh[kk], bh);
            mma16816(o[q*2+1], qh[kk], bh + 2);
        }
    }

    const int r0 = lane >> 2, ec = (lane & 3) * 2;
    #pragma unroll
    for (int nf = 0; nf < 4; nf++) {
        size_t p0 = base + (size_t)(m_base + r0) * DIMM + nf * 8 + ec;
        *(float2*)&out[p0]              = make_float2(o[nf][0], o[nf][1]);
        *(float2*)&out[p0 + 8 * DIMM]   = make_float2(o[nf][2], o[nf][3]);
    }
}

// ---------------- launch ---------------------------------------------------
extern "C" void kernel_launch(void* const* d_in, const int* in_sizes, int n_in,
                              void* d_out, int out_size)
{
    const float* query = (const float*)d_in[0];
    const float* key   = (const float*)d_in[1];
    const float* Wq    = (const float*)d_in[2];
    const float* Wk    = (const float*)d_in[3];
    const float* Wv    = (const float*)d_in[4];
    float* out = (float*)d_out;

    cudaFuncSetAttribute(proj_mma, cudaFuncAttributeMaxDynamicSharedMemorySize,
                         PROJ_SMEM_BYTES);
    cudaFuncSetAttribute(chunk_attn, cudaFuncAttributeMaxDynamicSharedMemorySize,
                         ATTN_SMEM_BYTES);

    // 0) convert W fp32 -> fp16 (X converted inside proj)
    {
        const size_t WQ = (size_t)DIMM * DIMM / 4;
        int blocks = (int)((3 * WQ + 255) / 256);
        cvt_w<<<blocks, 256>>>(Wq, Wk, Wv);
    }
    // 1) projections + fused X cvt + softmax (fp16 HMMA, cp.async)
    proj_mma<<<dim3(DIMM / 128, MROWS / 128, 3), 256, PROJ_SMEM_BYTES>>>(query, key);
    // 2) per-chunk K^T V sums (cp.async fill)
    chunk_sum<<<dim3(CCH, HH, NB), 64>>>();
    // 3) intra-chunk causal attention (cp.async fill, own prefix) + output
    chunk_attn<<<dim3(CCH, HH, NB), 256, ATTN_SMEM_BYTES>>>(out);
}